// round 2
// baseline (speedup 1.0000x reference)
#include <cuda_runtime.h>
#include <cuda_bf16.h>

#define BATCH   16
#define NPTS    4096
#define DFEAT   64
#define NPOINT  1024
#define NSAMPLE 32
#define P_TOT   (BATCH*NPOINT*NSAMPLE)   // 524288
#define NBLK    (P_TOT/64)               // 8192

// ---------------- device scratch ----------------
__device__ float g_ptsT[(size_t)BATCH*NPTS*DFEAT];       // points transposed (B,N,64)
__device__ float g_xyzT[(size_t)BATCH*NPTS*3];           // xyz transposed (B,N,3)
__device__ float g_newxyz[(size_t)BATCH*NPOINT*3];       // sampled centroids (B,S,3)
__device__ int   g_gidx[(size_t)BATCH*NPOINT*NSAMPLE];   // ball query indices
__device__ float g_x1[(size_t)P_TOT*64];                 // layer1 pre-BN
__device__ float g_x2[(size_t)P_TOT*64];                 // layer2 pre-BN
__device__ float g_x3[(size_t)P_TOT*128];                // layer3 pre-BN
__device__ float g_part[(size_t)2*128*NBLK];             // per-block partial sum/sumsq
__device__ float g_scale[3*128];                         // folded BN scale per layer (off 0,128,256)
__device__ float g_shift[3*128];

// ---------------- prep: transpose points & xyz ----------------
__global__ void __launch_bounds__(256) prep_kernel(const float* __restrict__ xyz,
                                                   const float* __restrict__ pts) {
    int b = blockIdx.y, n0 = blockIdx.x * 64, tid = threadIdx.x;
    __shared__ float t[64][65];
    const float* src = pts + (size_t)b * DFEAT * NPTS;
#pragma unroll
    for (int j = 0; j < 16; j++) {
        int i = tid + j * 256;
        int c = i >> 6, n = i & 63;
        t[n][c] = src[(size_t)c * NPTS + n0 + n];
    }
    __syncthreads();
    float* dst = g_ptsT + ((size_t)b * NPTS + n0) * DFEAT;
#pragma unroll
    for (int j = 0; j < 16; j++) {
        int i = tid + j * 256;
        int n = i >> 6, c = i & 63;
        dst[i] = t[n][c];
    }
    if (tid < 192) {
        int c = tid / 64, n = tid % 64;
        g_xyzT[((size_t)b * NPTS + n0 + n) * 3 + c] =
            xyz[(size_t)b * 3 * NPTS + (size_t)c * NPTS + n0 + n];
    }
}

// ---------------- FPS ----------------
__global__ void __launch_bounds__(256) fps_kernel(const float* __restrict__ xyz,
                                                  float* __restrict__ out) {
    int b = blockIdx.x, tid = threadIdx.x;
    __shared__ float sx[NPTS], sy[NPTS], sz[NPTS];
    __shared__ float swv[8];
    __shared__ int   swi[8];
    __shared__ int   s_win;
    const float* base = xyz + (size_t)b * 3 * NPTS;
    for (int i = tid; i < NPTS; i += 256) {
        sx[i] = base[i]; sy[i] = base[NPTS + i]; sz[i] = base[2 * NPTS + i];
    }
    float dist[16];
#pragma unroll
    for (int j = 0; j < 16; j++) dist[j] = 1e10f;
    __syncthreads();
    int far = 0;
    for (int it = 0; it < NPOINT; it++) {
        float cx = sx[far], cy = sy[far], cz = sz[far];
        if (tid == 0) {
            out[(size_t)b * 3 * NPOINT + it]              = cx;
            out[(size_t)b * 3 * NPOINT + NPOINT + it]     = cy;
            out[(size_t)b * 3 * NPOINT + 2 * NPOINT + it] = cz;
            g_newxyz[((size_t)b * NPOINT + it) * 3 + 0] = cx;
            g_newxyz[((size_t)b * NPOINT + it) * 3 + 1] = cy;
            g_newxyz[((size_t)b * NPOINT + it) * 3 + 2] = cz;
        }
        float best = -1.f; int bi = 0;
#pragma unroll
        for (int j = 0; j < 16; j++) {
            int p = j * 256 + tid;
            float dx = sx[p] - cx, dy = sy[p] - cy, dz = sz[p] - cz;
            float d = __fadd_rn(__fadd_rn(__fmul_rn(dx, dx), __fmul_rn(dy, dy)), __fmul_rn(dz, dz));
            float dm = fminf(dist[j], d);
            dist[j] = dm;
            if (dm > best) { best = dm; bi = p; }
        }
#pragma unroll
        for (int o = 16; o; o >>= 1) {
            float ov = __shfl_down_sync(0xffffffffu, best, o);
            int   oi = __shfl_down_sync(0xffffffffu, bi, o);
            if (ov > best || (ov == best && oi < bi)) { best = ov; bi = oi; }
        }
        if ((tid & 31) == 0) { swv[tid >> 5] = best; swi[tid >> 5] = bi; }
        __syncthreads();
        if (tid < 8) {
            best = swv[tid]; bi = swi[tid];
#pragma unroll
            for (int o = 4; o; o >>= 1) {
                float ov = __shfl_down_sync(0xffu, best, o);
                int   oi = __shfl_down_sync(0xffu, bi, o);
                if (ov > best || (ov == best && oi < bi)) { best = ov; bi = oi; }
            }
            if (tid == 0) s_win = bi;
        }
        __syncthreads();
        far = s_win;
    }
}

// ---------------- ball query ----------------
__global__ void __launch_bounds__(256) ballq_kernel(const float* __restrict__ xyz) {
    int b = blockIdx.y, tid = threadIdx.x;
    __shared__ float sx[NPTS], sy[NPTS], sz[NPTS];
    const float* base = xyz + (size_t)b * 3 * NPTS;
    for (int i = tid; i < NPTS; i += 256) {
        sx[i] = base[i]; sy[i] = base[NPTS + i]; sz[i] = base[2 * NPTS + i];
    }
    __syncthreads();
    int w = tid >> 5, lane = tid & 31;
    const float R2 = 0.01f;
    for (int ci = 0; ci < 8; ci++) {
        int s = blockIdx.x * 64 + w * 8 + ci;
        const float* cp = g_newxyz + ((size_t)b * NPOINT + s) * 3;
        float cx = cp[0], cy = cp[1], cz = cp[2];
        float s2 = __fadd_rn(__fadd_rn(__fmul_rn(cx, cx), __fmul_rn(cy, cy)), __fmul_rn(cz, cz));
        int cnt = 0, first = 0;
        int* gb = g_gidx + ((size_t)b * NPOINT + s) * NSAMPLE;
        for (int basei = 0; basei < NPTS; basei += 32) {
            int p = basei + lane;
            float x = sx[p], y = sy[p], z = sz[p];
            float p2 = __fadd_rn(__fadd_rn(__fmul_rn(x, x), __fmul_rn(y, y)), __fmul_rn(z, z));
            float dot = x * cx + y * cy + z * cz;
            float d = __fadd_rn(__fadd_rn(__fmul_rn(-2.f, dot), s2), p2);
            bool ok = !(d > R2);
            unsigned m = __ballot_sync(0xffffffffu, ok);
            if (cnt == 0 && m) first = basei + __ffs(m) - 1;
            int r = __popc(m & ((1u << lane) - 1u));
            if (ok && cnt + r < 32) gb[cnt + r] = p;
            cnt += __popc(m);
            if (cnt >= 32) break;
        }
        if (cnt < 32) {
            int j = cnt + lane;
            if (j < 32) gb[j] = first;
        }
    }
}

// ---------------- layer 1: gather + GEMM(67->64) + stats ----------------
__global__ void __launch_bounds__(256) l1_kernel(const float* __restrict__ W0,
                                                 const float* __restrict__ b0) {
    __shared__ float fs[64][68];
    __shared__ float ws[68][68];
    __shared__ float sred[16][64];
    __shared__ float sb[64];
    int tid = threadIdx.x, bx = blockIdx.x;
    int p0 = bx * 64;
    for (int i = tid; i < 64 * 67; i += 256) ws[i % 67][i / 67] = W0[i];
    if (tid < 64) sb[tid] = b0[tid];
    {
        int r = tid >> 2, tq = tid & 3;
        int p = p0 + r;
        int bb = p >> 15;
        int s = (p >> 5) & 1023;
        int idx = g_gidx[p];
        const float* pr = g_ptsT + ((size_t)bb * NPTS + idx) * 64 + tq * 16;
#pragma unroll
        for (int i = 0; i < 4; i++) {
            float4 v = *(const float4*)(pr + i * 4);
            int c = 3 + tq * 16 + i * 4;
            fs[r][c] = v.x; fs[r][c + 1] = v.y; fs[r][c + 2] = v.z; fs[r][c + 3] = v.w;
        }
        if (tq == 0) {
            const float* xr = g_xyzT + ((size_t)bb * NPTS + idx) * 3;
            const float* nr = g_newxyz + ((size_t)bb * NPOINT + s) * 3;
            fs[r][0] = xr[0] - nr[0];
            fs[r][1] = xr[1] - nr[1];
            fs[r][2] = xr[2] - nr[2];
        }
    }
    __syncthreads();
    int c0 = (tid & 15) * 4, r0 = (tid >> 4) * 4;
    float acc[4][4];
#pragma unroll
    for (int i = 0; i < 4; i++)
#pragma unroll
        for (int j = 0; j < 4; j++) acc[i][j] = sb[c0 + j];
#pragma unroll 4
    for (int k = 0; k < 67; k++) {
        float4 w4 = *(const float4*)&ws[k][c0];
        float f0 = fs[r0][k], f1 = fs[r0 + 1][k], f2 = fs[r0 + 2][k], f3 = fs[r0 + 3][k];
        acc[0][0] = fmaf(f0, w4.x, acc[0][0]); acc[0][1] = fmaf(f0, w4.y, acc[0][1]);
        acc[0][2] = fmaf(f0, w4.z, acc[0][2]); acc[0][3] = fmaf(f0, w4.w, acc[0][3]);
        acc[1][0] = fmaf(f1, w4.x, acc[1][0]); acc[1][1] = fmaf(f1, w4.y, acc[1][1]);
        acc[1][2] = fmaf(f1, w4.z, acc[1][2]); acc[1][3] = fmaf(f1, w4.w, acc[1][3]);
        acc[2][0] = fmaf(f2, w4.x, acc[2][0]); acc[2][1] = fmaf(f2, w4.y, acc[2][1]);
        acc[2][2] = fmaf(f2, w4.z, acc[2][2]); acc[2][3] = fmaf(f2, w4.w, acc[2][3]);
        acc[3][0] = fmaf(f3, w4.x, acc[3][0]); acc[3][1] = fmaf(f3, w4.y, acc[3][1]);
        acc[3][2] = fmaf(f3, w4.z, acc[3][2]); acc[3][3] = fmaf(f3, w4.w, acc[3][3]);
    }
#pragma unroll
    for (int i = 0; i < 4; i++) {
        float4 o; o.x = acc[i][0]; o.y = acc[i][1]; o.z = acc[i][2]; o.w = acc[i][3];
        *(float4*)(g_x1 + (size_t)(p0 + r0 + i) * 64 + c0) = o;
    }
    // deterministic per-block stats
    float ps[4], pq[4];
#pragma unroll
    for (int j = 0; j < 4; j++) {
        ps[j] = ((acc[0][j] + acc[1][j]) + acc[2][j]) + acc[3][j];
        pq[j] = ((acc[0][j] * acc[0][j] + acc[1][j] * acc[1][j]) + acc[2][j] * acc[2][j]) + acc[3][j] * acc[3][j];
    }
    int pg = tid >> 4;
#pragma unroll
    for (int j = 0; j < 4; j++) sred[pg][c0 + j] = ps[j];
    __syncthreads();
    if (tid < 64) {
        float s = 0.f;
#pragma unroll
        for (int g = 0; g < 16; g++) s += sred[g][tid];
        g_part[(size_t)tid * NBLK + bx] = s;
    }
    __syncthreads();
#pragma unroll
    for (int j = 0; j < 4; j++) sred[pg][c0 + j] = pq[j];
    __syncthreads();
    if (tid < 64) {
        float s = 0.f;
#pragma unroll
        for (int g = 0; g < 16; g++) s += sred[g][tid];
        g_part[(size_t)(64 + tid) * NBLK + bx] = s;
    }
}

// ---------------- fold BN stats into affine ----------------
__global__ void __launch_bounds__(256) fold_kernel(const float* __restrict__ gamma,
                                                   const float* __restrict__ beta,
                                                   int ch_tot, int off) {
    int c = blockIdx.x, tid = threadIdx.x;
    __shared__ float sh1[256], sh2[256];
    float s = 0.f, q = 0.f;
    for (int i = tid; i < NBLK; i += 256) {
        s += g_part[(size_t)c * NBLK + i];
        q += g_part[(size_t)(ch_tot + c) * NBLK + i];
    }
    sh1[tid] = s; sh2[tid] = q;
    __syncthreads();
    for (int o = 128; o; o >>= 1) {
        if (tid < o) { sh1[tid] += sh1[tid + o]; sh2[tid] += sh2[tid + o]; }
        __syncthreads();
    }
    if (tid == 0) {
        float n = (float)P_TOT;
        float mu = sh1[0] / n;
        float var = sh2[0] / n - mu * mu;
        float rs = rsqrtf(var + 1e-5f);
        float sc = gamma[c] * rs;
        g_scale[off + c] = sc;
        g_shift[off + c] = fmaf(-mu, sc, beta[c]);
    }
}

// ---------------- generic layer: affine+relu on load, GEMM(64->64 slice), stats ----------------
__global__ void __launch_bounds__(256) mlp_kernel(const float* __restrict__ xin,
                                                  const float* __restrict__ W,
                                                  const float* __restrict__ bias,
                                                  int in_off,
                                                  float* __restrict__ xout,
                                                  int ch_tot, int ch_stride) {
    __shared__ float xs[64][68];
    __shared__ float ws[64][68];
    __shared__ float sred[16][64];
    __shared__ float sb[64];
    int tid = threadIdx.x, bx = blockIdx.x;
    int cbase = blockIdx.y * 64;
    int p0 = bx * 64;
    for (int i = tid; i < 64 * 64; i += 256) {
        int c = i >> 6, k = i & 63;
        ws[k][c] = W[(size_t)(cbase + c) * 64 + k];
    }
    if (tid < 64) sb[tid] = bias[cbase + tid];
    {
        int r = tid >> 2, tq = tid & 3;
        const float* src = xin + (size_t)(p0 + r) * 64 + tq * 16;
#pragma unroll
        for (int i = 0; i < 4; i++) {
            float4 v = *(const float4*)(src + i * 4);
            int c = tq * 16 + i * 4;
            v.x = fmaxf(fmaf(v.x, g_scale[in_off + c + 0], g_shift[in_off + c + 0]), 0.f);
            v.y = fmaxf(fmaf(v.y, g_scale[in_off + c + 1], g_shift[in_off + c + 1]), 0.f);
            v.z = fmaxf(fmaf(v.z, g_scale[in_off + c + 2], g_shift[in_off + c + 2]), 0.f);
            v.w = fmaxf(fmaf(v.w, g_scale[in_off + c + 3], g_shift[in_off + c + 3]), 0.f);
            *(float4*)&xs[r][c] = v;
        }
    }
    __syncthreads();
    int c0 = (tid & 15) * 4, r0 = (tid >> 4) * 4;
    float acc[4][4];
#pragma unroll
    for (int i = 0; i < 4; i++)
#pragma unroll
        for (int j = 0; j < 4; j++) acc[i][j] = sb[c0 + j];
#pragma unroll 4
    for (int k = 0; k < 64; k++) {
        float4 w4 = *(const float4*)&ws[k][c0];
        float f0 = xs[r0][k], f1 = xs[r0 + 1][k], f2 = xs[r0 + 2][k], f3 = xs[r0 + 3][k];
        acc[0][0] = fmaf(f0, w4.x, acc[0][0]); acc[0][1] = fmaf(f0, w4.y, acc[0][1]);
        acc[0][2] = fmaf(f0, w4.z, acc[0][2]); acc[0][3] = fmaf(f0, w4.w, acc[0][3]);
        acc[1][0] = fmaf(f1, w4.x, acc[1][0]); acc[1][1] = fmaf(f1, w4.y, acc[1][1]);
        acc[1][2] = fmaf(f1, w4.z, acc[1][2]); acc[1][3] = fmaf(f1, w4.w, acc[1][3]);
        acc[2][0] = fmaf(f2, w4.x, acc[2][0]); acc[2][1] = fmaf(f2, w4.y, acc[2][1]);
        acc[2][2] = fmaf(f2, w4.z, acc[2][2]); acc[2][3] = fmaf(f2, w4.w, acc[2][3]);
        acc[3][0] = fmaf(f3, w4.x, acc[3][0]); acc[3][1] = fmaf(f3, w4.y, acc[3][1]);
        acc[3][2] = fmaf(f3, w4.z, acc[3][2]); acc[3][3] = fmaf(f3, w4.w, acc[3][3]);
    }
#pragma unroll
    for (int i = 0; i < 4; i++) {
        float4 o; o.x = acc[i][0]; o.y = acc[i][1]; o.z = acc[i][2]; o.w = acc[i][3];
        *(float4*)(xout + (size_t)(p0 + r0 + i) * ch_stride + cbase + c0) = o;
    }
    float ps[4], pq[4];
#pragma unroll
    for (int j = 0; j < 4; j++) {
        ps[j] = ((acc[0][j] + acc[1][j]) + acc[2][j]) + acc[3][j];
        pq[j] = ((acc[0][j] * acc[0][j] + acc[1][j] * acc[1][j]) + acc[2][j] * acc[2][j]) + acc[3][j] * acc[3][j];
    }
    int pg = tid >> 4;
#pragma unroll
    for (int j = 0; j < 4; j++) sred[pg][c0 + j] = ps[j];
    __syncthreads();
    if (tid < 64) {
        float s = 0.f;
#pragma unroll
        for (int g = 0; g < 16; g++) s += sred[g][tid];
        g_part[(size_t)(cbase + tid) * NBLK + bx] = s;
    }
    __syncthreads();
#pragma unroll
    for (int j = 0; j < 4; j++) sred[pg][c0 + j] = pq[j];
    __syncthreads();
    if (tid < 64) {
        float s = 0.f;
#pragma unroll
        for (int g = 0; g < 16; g++) s += sred[g][tid];
        g_part[(size_t)(ch_tot + cbase + tid) * NBLK + bx] = s;
    }
}

// ---------------- final BN + ReLU + maxpool over K ----------------
__global__ void __launch_bounds__(128) maxpool_kernel(float* __restrict__ out2) {
    int g0 = blockIdx.x * 16, tid = threadIdx.x;
    float sc = g_scale[256 + tid], sh = g_shift[256 + tid];
    float m[16];
#pragma unroll
    for (int gi = 0; gi < 16; gi++) {
        size_t prow = (size_t)(g0 + gi) * 32;
        float mm = 0.f;
#pragma unroll 8
        for (int k = 0; k < 32; k++) {
            float v = g_x3[(prow + k) * 128 + tid];
            mm = fmaxf(mm, fmaxf(fmaf(v, sc, sh), 0.f));
        }
        m[gi] = mm;
    }
    int b = g0 >> 10;
    int s0 = g0 & 1023;
    float* dst = out2 + ((size_t)b * 128 + tid) * NPOINT + s0;
#pragma unroll
    for (int i = 0; i < 4; i++) {
        float4 o; o.x = m[i * 4]; o.y = m[i * 4 + 1]; o.z = m[i * 4 + 2]; o.w = m[i * 4 + 3];
        *(float4*)(dst + i * 4) = o;
    }
}

// ---------------- launch ----------------
extern "C" void kernel_launch(void* const* d_in, const int* in_sizes, int n_in,
                              void* d_out, int out_size) {
    const float* xyz = (const float*)d_in[0];
    const float* pts = (const float*)d_in[1];
    const float* W0 = (const float*)d_in[2];  const float* b0 = (const float*)d_in[3];
    const float* ga0 = (const float*)d_in[4]; const float* be0 = (const float*)d_in[5];
    const float* W1 = (const float*)d_in[6];  const float* b1 = (const float*)d_in[7];
    const float* ga1 = (const float*)d_in[8]; const float* be1 = (const float*)d_in[9];
    const float* W2 = (const float*)d_in[10]; const float* b2 = (const float*)d_in[11];
    const float* ga2 = (const float*)d_in[12]; const float* be2 = (const float*)d_in[13];
    float* out = (float*)d_out;
    float* out2 = out + (size_t)BATCH * 3 * NPOINT;

    float* d_x1; cudaGetSymbolAddress((void**)&d_x1, g_x1);
    float* d_x2; cudaGetSymbolAddress((void**)&d_x2, g_x2);
    float* d_x3; cudaGetSymbolAddress((void**)&d_x3, g_x3);

    prep_kernel<<<dim3(64, 16), 256>>>(xyz, pts);
    fps_kernel<<<16, 256>>>(xyz, out);
    ballq_kernel<<<dim3(16, 16), 256>>>(xyz);

    l1_kernel<<<NBLK, 256>>>(W0, b0);
    fold_kernel<<<64, 256>>>(ga0, be0, 64, 0);

    mlp_kernel<<<dim3(NBLK, 1), 256>>>(d_x1, W1, b1, 0, d_x2, 64, 64);
    fold_kernel<<<64, 256>>>(ga1, be1, 64, 128);

    mlp_kernel<<<dim3(NBLK, 2), 256>>>(d_x2, W2, b2, 128, d_x3, 128, 128);
    fold_kernel<<<128, 256>>>(ga2, be2, 128, 256);

    maxpool_kernel<<<BATCH * NPOINT / 16, 128>>>(out2);
}

// round 3
// speedup vs baseline: 1.0411x; 1.0411x over previous
#include <cuda_runtime.h>
#include <cuda_bf16.h>

#define BATCH   16
#define NPTS    4096
#define DFEAT   64
#define NPOINT  1024
#define NSAMPLE 32
#define P_TOT   (BATCH*NPOINT*NSAMPLE)   // 524288
#define PBLK    (P_TOT/128)              // 4096 row-tiles of 128

// ---------------- device scratch ----------------
__device__ float g_ptsT[(size_t)BATCH*NPTS*DFEAT];
__device__ float g_xyzT[(size_t)BATCH*NPTS*3];
__device__ float g_newxyz[(size_t)BATCH*NPOINT*3];
__device__ int   g_gidx[(size_t)BATCH*NPOINT*NSAMPLE];
__device__ float g_x1[(size_t)P_TOT*64];
__device__ float g_x2[(size_t)P_TOT*64];
__device__ float g_x3[(size_t)P_TOT*128];
__device__ float g_part[(size_t)2*128*PBLK];
__device__ float g_scale[3*128];
__device__ float g_shift[3*128];

// ---------------- prep: transpose points & xyz ----------------
__global__ void __launch_bounds__(256) prep_kernel(const float* __restrict__ xyz,
                                                   const float* __restrict__ pts) {
    int b = blockIdx.y, n0 = blockIdx.x * 64, tid = threadIdx.x;
    __shared__ float t[64][65];
    const float* src = pts + (size_t)b * DFEAT * NPTS;
#pragma unroll
    for (int j = 0; j < 16; j++) {
        int i = tid + j * 256;
        int c = i >> 6, n = i & 63;
        t[n][c] = src[(size_t)c * NPTS + n0 + n];
    }
    __syncthreads();
    float* dst = g_ptsT + ((size_t)b * NPTS + n0) * DFEAT;
#pragma unroll
    for (int j = 0; j < 16; j++) {
        int i = tid + j * 256;
        int n = i >> 6, c = i & 63;
        dst[i] = t[n][c];
    }
    if (tid < 192) {
        int c = tid / 64, n = tid % 64;
        g_xyzT[((size_t)b * NPTS + n0 + n) * 3 + c] =
            xyz[(size_t)b * 3 * NPTS + (size_t)c * NPTS + n0 + n];
    }
}

// ---------------- FPS (coords in registers; smem only for centroid lookup) ---
__global__ void __launch_bounds__(256) fps_kernel(const float* __restrict__ xyz,
                                                  float* __restrict__ out) {
    int b = blockIdx.x, tid = threadIdx.x;
    __shared__ float sx[NPTS], sy[NPTS], sz[NPTS];
    __shared__ float swv[8];
    __shared__ int   swi[8];
    __shared__ int   s_win;
    const float* base = xyz + (size_t)b * 3 * NPTS;
    for (int i = tid; i < NPTS; i += 256) {
        sx[i] = base[i]; sy[i] = base[NPTS + i]; sz[i] = base[2 * NPTS + i];
    }
    float px[16], py[16], pz[16], dist[16];
#pragma unroll
    for (int j = 0; j < 16; j++) {
        int p = j * 256 + tid;
        px[j] = base[p]; py[j] = base[NPTS + p]; pz[j] = base[2 * NPTS + p];
        dist[j] = 1e10f;
    }
    __syncthreads();
    int far = 0;
    for (int it = 0; it < NPOINT; it++) {
        float cx = sx[far], cy = sy[far], cz = sz[far];
        if (tid == 0) {
            out[(size_t)b * 3 * NPOINT + it]              = cx;
            out[(size_t)b * 3 * NPOINT + NPOINT + it]     = cy;
            out[(size_t)b * 3 * NPOINT + 2 * NPOINT + it] = cz;
            g_newxyz[((size_t)b * NPOINT + it) * 3 + 0] = cx;
            g_newxyz[((size_t)b * NPOINT + it) * 3 + 1] = cy;
            g_newxyz[((size_t)b * NPOINT + it) * 3 + 2] = cz;
        }
        float best = -1.f; int bi = 0;
#pragma unroll
        for (int j = 0; j < 16; j++) {
            float dx = px[j] - cx, dy = py[j] - cy, dz = pz[j] - cz;
            float d = __fadd_rn(__fadd_rn(__fmul_rn(dx, dx), __fmul_rn(dy, dy)), __fmul_rn(dz, dz));
            float dm = fminf(dist[j], d);
            dist[j] = dm;
            if (dm > best) { best = dm; bi = j * 256 + tid; }
        }
#pragma unroll
        for (int o = 16; o; o >>= 1) {
            float ov = __shfl_down_sync(0xffffffffu, best, o);
            int   oi = __shfl_down_sync(0xffffffffu, bi, o);
            if (ov > best || (ov == best && oi < bi)) { best = ov; bi = oi; }
        }
        if ((tid & 31) == 0) { swv[tid >> 5] = best; swi[tid >> 5] = bi; }
        __syncthreads();
        if (tid < 8) {
            best = swv[tid]; bi = swi[tid];
#pragma unroll
            for (int o = 4; o; o >>= 1) {
                float ov = __shfl_down_sync(0xffu, best, o);
                int   oi = __shfl_down_sync(0xffu, bi, o);
                if (ov > best || (ov == best && oi < bi)) { best = ov; bi = oi; }
            }
            if (tid == 0) s_win = bi;
        }
        __syncthreads();
        far = s_win;
    }
}

// ---------------- ball query (unchanged numerics) ----------------
__global__ void __launch_bounds__(256) ballq_kernel(const float* __restrict__ xyz) {
    int b = blockIdx.y, tid = threadIdx.x;
    __shared__ float sx[NPTS], sy[NPTS], sz[NPTS];
    const float* base = xyz + (size_t)b * 3 * NPTS;
    for (int i = tid; i < NPTS; i += 256) {
        sx[i] = base[i]; sy[i] = base[NPTS + i]; sz[i] = base[2 * NPTS + i];
    }
    __syncthreads();
    int w = tid >> 5, lane = tid & 31;
    const float R2 = 0.01f;
    for (int ci = 0; ci < 8; ci++) {
        int s = blockIdx.x * 64 + w * 8 + ci;
        const float* cp = g_newxyz + ((size_t)b * NPOINT + s) * 3;
        float cx = cp[0], cy = cp[1], cz = cp[2];
        float s2 = __fadd_rn(__fadd_rn(__fmul_rn(cx, cx), __fmul_rn(cy, cy)), __fmul_rn(cz, cz));
        int cnt = 0, first = 0;
        int* gb = g_gidx + ((size_t)b * NPOINT + s) * NSAMPLE;
        for (int basei = 0; basei < NPTS; basei += 32) {
            int p = basei + lane;
            float x = sx[p], y = sy[p], z = sz[p];
            float p2 = __fadd_rn(__fadd_rn(__fmul_rn(x, x), __fmul_rn(y, y)), __fmul_rn(z, z));
            float dot = x * cx + y * cy + z * cz;
            float d = __fadd_rn(__fadd_rn(__fmul_rn(-2.f, dot), s2), p2);
            bool ok = !(d > R2);
            unsigned m = __ballot_sync(0xffffffffu, ok);
            if (cnt == 0 && m) first = basei + __ffs(m) - 1;
            int r = __popc(m & ((1u << lane) - 1u));
            if (ok && cnt + r < 32) gb[cnt + r] = p;
            cnt += __popc(m);
            if (cnt >= 32) break;
        }
        if (cnt < 32) {
            int j = cnt + lane;
            if (j < 32) gb[j] = first;
        }
    }
}

// ============ layer 1: gather + GEMM (68-pad K -> 64) + stats ============
// fs layout: cols 0..63 = features, 64..66 = xyz diff, 67 = zero pad
#define FS_STRIDE 68
__global__ void __launch_bounds__(256) l1_kernel(const float* __restrict__ W0,
                                                 const float* __restrict__ b0) {
    extern __shared__ float sm[];
    float* fs = sm;                       // 128 x 68
    float* ws = sm + 128 * FS_STRIDE;     // 68 x 64
    __shared__ float sred[16][64];
    __shared__ float sb[64];
    int tid = threadIdx.x, bx = blockIdx.x;
    int p0 = bx * 128;
    for (int i = tid; i < 64 * 67; i += 256) {
        int c = i / 67, ko = i % 67;
        int kn = ko < 3 ? 64 + ko : ko - 3;
        ws[kn * 64 + c] = W0[i];
    }
    if (tid < 64) { ws[67 * 64 + tid] = 0.f; sb[tid] = b0[tid]; }
    {
        int r = tid >> 1, h = tid & 1;
        int p = p0 + r;
        int bb = p >> 15;
        int s = (p >> 5) & 1023;
        int idx = g_gidx[p];
        const float* pr = g_ptsT + ((size_t)bb * NPTS + idx) * 64 + h * 32;
#pragma unroll
        for (int i = 0; i < 8; i++)
            *(float4*)&fs[r * FS_STRIDE + h * 32 + i * 4] = *(const float4*)(pr + i * 4);
        if (h == 0) {
            const float* xr = g_xyzT + ((size_t)bb * NPTS + idx) * 3;
            const float* nr = g_newxyz + ((size_t)bb * NPOINT + s) * 3;
            fs[r * FS_STRIDE + 64] = xr[0] - nr[0];
            fs[r * FS_STRIDE + 65] = xr[1] - nr[1];
            fs[r * FS_STRIDE + 66] = xr[2] - nr[2];
        } else {
            fs[r * FS_STRIDE + 67] = 0.f;
        }
    }
    __syncthreads();
    int c0 = (tid & 15) * 4, r0 = (tid >> 4) * 8;
    float acc[8][4];
#pragma unroll
    for (int i = 0; i < 8; i++)
#pragma unroll
        for (int j = 0; j < 4; j++) acc[i][j] = sb[c0 + j];
    for (int k4 = 0; k4 < 68; k4 += 4) {
        float4 f[8];
#pragma unroll
        for (int i = 0; i < 8; i++) f[i] = *(float4*)&fs[(r0 + i) * FS_STRIDE + k4];
#pragma unroll
        for (int j = 0; j < 4; j++) {
            float4 w = *(float4*)&ws[(k4 + j) * 64 + c0];
#pragma unroll
            for (int i = 0; i < 8; i++) {
                float fv = j == 0 ? f[i].x : j == 1 ? f[i].y : j == 2 ? f[i].z : f[i].w;
                acc[i][0] = fmaf(fv, w.x, acc[i][0]);
                acc[i][1] = fmaf(fv, w.y, acc[i][1]);
                acc[i][2] = fmaf(fv, w.z, acc[i][2]);
                acc[i][3] = fmaf(fv, w.w, acc[i][3]);
            }
        }
    }
#pragma unroll
    for (int i = 0; i < 8; i++) {
        float4 o; o.x = acc[i][0]; o.y = acc[i][1]; o.z = acc[i][2]; o.w = acc[i][3];
        *(float4*)(g_x1 + (size_t)(p0 + r0 + i) * 64 + c0) = o;
    }
    float ps[4], pq[4];
#pragma unroll
    for (int j = 0; j < 4; j++) {
        float s = 0.f, q = 0.f;
#pragma unroll
        for (int i = 0; i < 8; i++) { s += acc[i][j]; q += acc[i][j] * acc[i][j]; }
        ps[j] = s; pq[j] = q;
    }
    int pg = tid >> 4;
#pragma unroll
    for (int j = 0; j < 4; j++) sred[pg][c0 + j] = ps[j];
    __syncthreads();
    if (tid < 64) {
        float s = 0.f;
#pragma unroll
        for (int g = 0; g < 16; g++) s += sred[g][tid];
        g_part[(size_t)tid * PBLK + bx] = s;
    }
    __syncthreads();
#pragma unroll
    for (int j = 0; j < 4; j++) sred[pg][c0 + j] = pq[j];
    __syncthreads();
    if (tid < 64) {
        float s = 0.f;
#pragma unroll
        for (int g = 0; g < 16; g++) s += sred[g][tid];
        g_part[(size_t)(64 + tid) * PBLK + bx] = s;
    }
}

// ---------------- fold BN stats into affine ----------------
__global__ void __launch_bounds__(256) fold_kernel(const float* __restrict__ gamma,
                                                   const float* __restrict__ beta,
                                                   int ch_tot, int off) {
    int c = blockIdx.x, tid = threadIdx.x;
    __shared__ float sh1[256], sh2[256];
    float s = 0.f, q = 0.f;
    for (int i = tid; i < PBLK; i += 256) {
        s += g_part[(size_t)c * PBLK + i];
        q += g_part[(size_t)(ch_tot + c) * PBLK + i];
    }
    sh1[tid] = s; sh2[tid] = q;
    __syncthreads();
    for (int o = 128; o; o >>= 1) {
        if (tid < o) { sh1[tid] += sh1[tid + o]; sh2[tid] += sh2[tid + o]; }
        __syncthreads();
    }
    if (tid == 0) {
        float n = (float)P_TOT;
        float mu = sh1[0] / n;
        float var = sh2[0] / n - mu * mu;
        float rs = rsqrtf(var + 1e-5f);
        float sc = gamma[c] * rs;
        g_scale[off + c] = sc;
        g_shift[off + c] = fmaf(-mu, sc, beta[c]);
    }
}

// ============ layer2: affine+relu load, 64->64 GEMM, stats ============
__global__ void __launch_bounds__(256) mlp64_kernel(const float* __restrict__ xin,
                                                    const float* __restrict__ W,
                                                    const float* __restrict__ bias,
                                                    int in_off,
                                                    float* __restrict__ xout) {
    extern __shared__ float sm[];
    float* xs = sm;                       // 128 x 68
    float* ws = sm + 128 * FS_STRIDE;     // 64 x 64
    __shared__ float sred[16][64];
    __shared__ float sb[64];
    int tid = threadIdx.x, bx = blockIdx.x;
    int p0 = bx * 128;
    for (int i = tid; i < 64 * 64; i += 256) {
        int c = i >> 6, k = i & 63;
        ws[k * 64 + c] = W[i];
    }
    if (tid < 64) sb[tid] = bias[tid];
    {
        int r = tid >> 1, h = tid & 1;
        const float* src = xin + (size_t)(p0 + r) * 64 + h * 32;
#pragma unroll
        for (int i = 0; i < 8; i++) {
            float4 v = *(const float4*)(src + i * 4);
            int c = h * 32 + i * 4;
            v.x = fmaxf(fmaf(v.x, g_scale[in_off + c + 0], g_shift[in_off + c + 0]), 0.f);
            v.y = fmaxf(fmaf(v.y, g_scale[in_off + c + 1], g_shift[in_off + c + 1]), 0.f);
            v.z = fmaxf(fmaf(v.z, g_scale[in_off + c + 2], g_shift[in_off + c + 2]), 0.f);
            v.w = fmaxf(fmaf(v.w, g_scale[in_off + c + 3], g_shift[in_off + c + 3]), 0.f);
            *(float4*)&xs[r * FS_STRIDE + c] = v;
        }
    }
    __syncthreads();
    int c0 = (tid & 15) * 4, r0 = (tid >> 4) * 8;
    float acc[8][4];
#pragma unroll
    for (int i = 0; i < 8; i++)
#pragma unroll
        for (int j = 0; j < 4; j++) acc[i][j] = sb[c0 + j];
    for (int k4 = 0; k4 < 64; k4 += 4) {
        float4 f[8];
#pragma unroll
        for (int i = 0; i < 8; i++) f[i] = *(float4*)&xs[(r0 + i) * FS_STRIDE + k4];
#pragma unroll
        for (int j = 0; j < 4; j++) {
            float4 w = *(float4*)&ws[(k4 + j) * 64 + c0];
#pragma unroll
            for (int i = 0; i < 8; i++) {
                float fv = j == 0 ? f[i].x : j == 1 ? f[i].y : j == 2 ? f[i].z : f[i].w;
                acc[i][0] = fmaf(fv, w.x, acc[i][0]);
                acc[i][1] = fmaf(fv, w.y, acc[i][1]);
                acc[i][2] = fmaf(fv, w.z, acc[i][2]);
                acc[i][3] = fmaf(fv, w.w, acc[i][3]);
            }
        }
    }
#pragma unroll
    for (int i = 0; i < 8; i++) {
        float4 o; o.x = acc[i][0]; o.y = acc[i][1]; o.z = acc[i][2]; o.w = acc[i][3];
        *(float4*)(xout + (size_t)(p0 + r0 + i) * 64 + c0) = o;
    }
    float ps[4], pq[4];
#pragma unroll
    for (int j = 0; j < 4; j++) {
        float s = 0.f, q = 0.f;
#pragma unroll
        for (int i = 0; i < 8; i++) { s += acc[i][j]; q += acc[i][j] * acc[i][j]; }
        ps[j] = s; pq[j] = q;
    }
    int pg = tid >> 4;
#pragma unroll
    for (int j = 0; j < 4; j++) sred[pg][c0 + j] = ps[j];
    __syncthreads();
    if (tid < 64) {
        float s = 0.f;
#pragma unroll
        for (int g = 0; g < 16; g++) s += sred[g][tid];
        g_part[(size_t)tid * PBLK + bx] = s;
    }
    __syncthreads();
#pragma unroll
    for (int j = 0; j < 4; j++) sred[pg][c0 + j] = pq[j];
    __syncthreads();
    if (tid < 64) {
        float s = 0.f;
#pragma unroll
        for (int g = 0; g < 16; g++) s += sred[g][tid];
        g_part[(size_t)(64 + tid) * PBLK + bx] = s;
    }
}

// ============ layer3: affine+relu load, 64->128 GEMM (full width), stats =====
__global__ void __launch_bounds__(256) mlp128_kernel(const float* __restrict__ xin,
                                                     const float* __restrict__ W,
                                                     const float* __restrict__ bias,
                                                     int in_off,
                                                     float* __restrict__ xout) {
    extern __shared__ float sm[];
    float* xs = sm;                       // 128 x 68
    float* ws = sm + 128 * FS_STRIDE;     // 64 x 128
    __shared__ float sred[16][128];
    __shared__ float sb[128];
    int tid = threadIdx.x, bx = blockIdx.x;
    int p0 = bx * 128;
    for (int i = tid; i < 128 * 64; i += 256) {
        int c = i >> 6, k = i & 63;
        ws[k * 128 + c] = W[i];
    }
    if (tid < 128) sb[tid] = bias[tid];
    {
        int r = tid >> 1, h = tid & 1;
        const float* src = xin + (size_t)(p0 + r) * 64 + h * 32;
#pragma unroll
        for (int i = 0; i < 8; i++) {
            float4 v = *(const float4*)(src + i * 4);
            int c = h * 32 + i * 4;
            v.x = fmaxf(fmaf(v.x, g_scale[in_off + c + 0], g_shift[in_off + c + 0]), 0.f);
            v.y = fmaxf(fmaf(v.y, g_scale[in_off + c + 1], g_shift[in_off + c + 1]), 0.f);
            v.z = fmaxf(fmaf(v.z, g_scale[in_off + c + 2], g_shift[in_off + c + 2]), 0.f);
            v.w = fmaxf(fmaf(v.w, g_scale[in_off + c + 3], g_shift[in_off + c + 3]), 0.f);
            *(float4*)&xs[r * FS_STRIDE + c] = v;
        }
    }
    __syncthreads();
    int c0 = (tid & 15) * 4, r0 = (tid >> 4) * 8;
    float acc[8][8];   // cols: c0..c0+3 and c0+64..c0+67
#pragma unroll
    for (int i = 0; i < 8; i++)
#pragma unroll
        for (int j = 0; j < 4; j++) {
            acc[i][j]     = sb[c0 + j];
            acc[i][j + 4] = sb[c0 + 64 + j];
        }
    for (int k4 = 0; k4 < 64; k4 += 4) {
        float4 f[8];
#pragma unroll
        for (int i = 0; i < 8; i++) f[i] = *(float4*)&xs[(r0 + i) * FS_STRIDE + k4];
#pragma unroll
        for (int j = 0; j < 4; j++) {
            float4 w0 = *(float4*)&ws[(k4 + j) * 128 + c0];
            float4 w1 = *(float4*)&ws[(k4 + j) * 128 + c0 + 64];
#pragma unroll
            for (int i = 0; i < 8; i++) {
                float fv = j == 0 ? f[i].x : j == 1 ? f[i].y : j == 2 ? f[i].z : f[i].w;
                acc[i][0] = fmaf(fv, w0.x, acc[i][0]);
                acc[i][1] = fmaf(fv, w0.y, acc[i][1]);
                acc[i][2] = fmaf(fv, w0.z, acc[i][2]);
                acc[i][3] = fmaf(fv, w0.w, acc[i][3]);
                acc[i][4] = fmaf(fv, w1.x, acc[i][4]);
                acc[i][5] = fmaf(fv, w1.y, acc[i][5]);
                acc[i][6] = fmaf(fv, w1.z, acc[i][6]);
                acc[i][7] = fmaf(fv, w1.w, acc[i][7]);
            }
        }
    }
#pragma unroll
    for (int i = 0; i < 8; i++) {
        float4 o0, o1;
        o0.x = acc[i][0]; o0.y = acc[i][1]; o0.z = acc[i][2]; o0.w = acc[i][3];
        o1.x = acc[i][4]; o1.y = acc[i][5]; o1.z = acc[i][6]; o1.w = acc[i][7];
        *(float4*)(xout + (size_t)(p0 + r0 + i) * 128 + c0)      = o0;
        *(float4*)(xout + (size_t)(p0 + r0 + i) * 128 + c0 + 64) = o1;
    }
    float ps[8], pq[8];
#pragma unroll
    for (int j = 0; j < 8; j++) {
        float s = 0.f, q = 0.f;
#pragma unroll
        for (int i = 0; i < 8; i++) { s += acc[i][j]; q += acc[i][j] * acc[i][j]; }
        ps[j] = s; pq[j] = q;
    }
    int pg = tid >> 4;
#pragma unroll
    for (int j = 0; j < 4; j++) {
        sred[pg][c0 + j]      = ps[j];
        sred[pg][c0 + 64 + j] = ps[j + 4];
    }
    __syncthreads();
    if (tid < 128) {
        float s = 0.f;
#pragma unroll
        for (int g = 0; g < 16; g++) s += sred[g][tid];
        g_part[(size_t)tid * PBLK + bx] = s;
    }
    __syncthreads();
#pragma unroll
    for (int j = 0; j < 4; j++) {
        sred[pg][c0 + j]      = pq[j];
        sred[pg][c0 + 64 + j] = pq[j + 4];
    }
    __syncthreads();
    if (tid < 128) {
        float s = 0.f;
#pragma unroll
        for (int g = 0; g < 16; g++) s += sred[g][tid];
        g_part[(size_t)(128 + tid) * PBLK + bx] = s;
    }
}

// ---------------- final BN + ReLU + maxpool over K ----------------
__global__ void __launch_bounds__(128) maxpool_kernel(float* __restrict__ out2) {
    int g0 = blockIdx.x * 16, tid = threadIdx.x;
    float sc = g_scale[256 + tid], sh = g_shift[256 + tid];
    float m[16];
#pragma unroll
    for (int gi = 0; gi < 16; gi++) {
        size_t prow = (size_t)(g0 + gi) * 32;
        float mm = 0.f;
#pragma unroll 8
        for (int k = 0; k < 32; k++) {
            float v = g_x3[(prow + k) * 128 + tid];
            mm = fmaxf(mm, fmaxf(fmaf(v, sc, sh), 0.f));
        }
        m[gi] = mm;
    }
    int b = g0 >> 10;
    int s0 = g0 & 1023;
    float* dst = out2 + ((size_t)b * 128 + tid) * NPOINT + s0;
#pragma unroll
    for (int i = 0; i < 4; i++) {
        float4 o; o.x = m[i * 4]; o.y = m[i * 4 + 1]; o.z = m[i * 4 + 2]; o.w = m[i * 4 + 3];
        *(float4*)(dst + i * 4) = o;
    }
}

// ---------------- launch ----------------
extern "C" void kernel_launch(void* const* d_in, const int* in_sizes, int n_in,
                              void* d_out, int out_size) {
    const float* xyz = (const float*)d_in[0];
    const float* pts = (const float*)d_in[1];
    const float* W0 = (const float*)d_in[2];  const float* b0 = (const float*)d_in[3];
    const float* ga0 = (const float*)d_in[4]; const float* be0 = (const float*)d_in[5];
    const float* W1 = (const float*)d_in[6];  const float* b1 = (const float*)d_in[7];
    const float* ga1 = (const float*)d_in[8]; const float* be1 = (const float*)d_in[9];
    const float* W2 = (const float*)d_in[10]; const float* b2 = (const float*)d_in[11];
    const float* ga2 = (const float*)d_in[12]; const float* be2 = (const float*)d_in[13];
    float* out = (float*)d_out;
    float* out2 = out + (size_t)BATCH * 3 * NPOINT;

    float* d_x1; cudaGetSymbolAddress((void**)&d_x1, g_x1);
    float* d_x2; cudaGetSymbolAddress((void**)&d_x2, g_x2);
    float* d_x3; cudaGetSymbolAddress((void**)&d_x3, g_x3);

    const int smem_l1  = (128 * FS_STRIDE + 68 * 64) * 4;
    const int smem_m64 = (128 * FS_STRIDE + 64 * 64) * 4;
    const int smem_m128 = (128 * FS_STRIDE + 64 * 128) * 4;
    cudaFuncSetAttribute(l1_kernel,     cudaFuncAttributeMaxDynamicSharedMemorySize, smem_l1);
    cudaFuncSetAttribute(mlp64_kernel,  cudaFuncAttributeMaxDynamicSharedMemorySize, smem_m64);
    cudaFuncSetAttribute(mlp128_kernel, cudaFuncAttributeMaxDynamicSharedMemorySize, smem_m128);

    prep_kernel<<<dim3(64, 16), 256>>>(xyz, pts);
    fps_kernel<<<16, 256>>>(xyz, out);
    ballq_kernel<<<dim3(16, 16), 256>>>(xyz);

    l1_kernel<<<PBLK, 256, smem_l1>>>(W0, b0);
    fold_kernel<<<64, 256>>>(ga0, be0, 64, 0);

    mlp64_kernel<<<PBLK, 256, smem_m64>>>(d_x1, W1, b1, 0, d_x2);
    fold_kernel<<<64, 256>>>(ga1, be1, 64, 128);

    mlp128_kernel<<<PBLK, 256, smem_m128>>>(d_x2, W2, b2, 128, d_x3);
    fold_kernel<<<128, 256>>>(ga2, be2, 128, 256);

    maxpool_kernel<<<BATCH * NPOINT / 16, 128>>>(out2);
}